// round 4
// baseline (speedup 1.0000x reference)
#include <cuda_runtime.h>
#include <cstdint>

#define NN 50000
#define EE 1600000
#define IN_C 128
#define HH 64
#define OUT_C 40
#define ALPHA 0.8f
#define LN_EPS 1e-5f

// Scratch (device globals; 16B-aligned via float4)
__device__ float4 g_xh4[NN * 16];
__device__ float4 g_xU4[NN * 16];
__device__ float4 g_h4 [NN * 16];
__device__ float4 g_a4 [NN * 16];
__device__ float4 g_z4 [NN * 16];
__device__ int    g_row[EE];
__device__ int    g_col[EE];
__device__ int    g_is64;
// pre-transposed weights
__device__ float  g_WeT[IN_C * HH];   // [k][c] = We[c][k]
__device__ float  g_UT [HH * HH];     // [k][c] = U[c][k]
__device__ float  g_WT [HH * HH];     // [k][c] = W[c][k]
__device__ float  g_WlT[HH * HH];     // [k][c] = Wl[c][k], zero-padded c>=40

#define g_xh ((float*)g_xh4)
#define g_a  ((float*)g_a4)
#define g_z  ((float*)g_z4)

__device__ __forceinline__ float htanh(float x) {
    float y;
    asm("tanh.approx.f32 %0, %1;" : "=f"(y) : "f"(x));
    return y;
}

// ---------------------------------------------------------------------------
__global__ void k_probe(const int* __restrict__ ei_raw) {
    if (threadIdx.x == 0 && blockIdx.x == 0) {
        int allzero = 1;
        #pragma unroll
        for (int i = 1; i < 128; i += 2) allzero &= (ei_raw[i] == 0);
        g_is64 = allzero;
    }
}

__global__ __launch_bounds__(256) void k_convert(const int* __restrict__ ei_raw) {
    int e = blockIdx.x * blockDim.x + threadIdx.x;
    if (e >= EE) return;
    if (g_is64) {
        const long long* p = (const long long*)ei_raw;
        g_row[e] = (int)p[e];
        g_col[e] = (int)p[EE + e];
    } else {
        g_row[e] = ei_raw[e];
        g_col[e] = ei_raw[EE + e];
    }
}

// ---------------------------------------------------------------------------
__global__ __launch_bounds__(256) void k_prep(const float* __restrict__ We,
                                              const float* __restrict__ U,
                                              const float* __restrict__ W,
                                              const float* __restrict__ Wl) {
    int idx = blockIdx.x * blockDim.x + threadIdx.x;
    if (idx < IN_C * HH) {
        int k = idx >> 6, c = idx & 63;
        g_WeT[idx] = We[c * IN_C + k];
    }
    if (idx < HH * HH) {
        int k = idx >> 6, c = idx & 63;
        g_UT[idx]  = U[c * HH + k];
        g_WT[idx]  = W[c * HH + k];
        g_WlT[idx] = (c < OUT_C) ? Wl[c * HH + k] : 0.0f;
    }
}

// ---------------------------------------------------------------------------
// Front: xh = x@We^T + be ; xU = deg*(xh@U^T + bU) ; h0 = nf*xU ; z=0 ; a=0
// 128 nodes/block, 256 threads; thread: 4 nodes x 8 channels.
// dyn smem: Xs[128*129] | Wes[128*64] | Uts[64*64]   (= 115.2 KB)
// ---------------------------------------------------------------------------
__global__ __launch_bounds__(256) void k_front(const float* __restrict__ x,
                                               const float* __restrict__ be,
                                               const float* __restrict__ bU,
                                               const float* __restrict__ nf) {
    extern __shared__ float sm[];
    float* Xs  = sm;                 // 128 * 129
    float* Wes = sm + 128 * 129;     // 128 * 64
    float* Uts = Wes + IN_C * HH;    // 64 * 64

    int tid = threadIdx.x;
    int g = tid & 7, nb = tid >> 3;
    int base = blockIdx.x * 128;

    for (int idx = tid; idx < 128 * IN_C; idx += 256) {
        int n = idx >> 7, k = idx & 127;
        Xs[n * 129 + k] = (base + n < NN) ? x[(base + n) * IN_C + k] : 0.0f;
    }
    for (int idx = tid; idx < IN_C * HH; idx += 256) Wes[idx] = g_WeT[idx];
    for (int idx = tid; idx < HH * HH; idx += 256)  Uts[idx] = g_UT[idx];
    __syncthreads();

    const float4* Wes4 = (const float4*)Wes;
    const float4* Uts4 = (const float4*)Uts;
    float4 beA = ((const float4*)be)[2 * g], beB = ((const float4*)be)[2 * g + 1];
    float4 bUA = ((const float4*)bU)[2 * g], bUB = ((const float4*)bU)[2 * g + 1];

    float4 aA[4], aB[4];
    #pragma unroll
    for (int j = 0; j < 4; j++) { aA[j] = make_float4(0,0,0,0); aB[j] = make_float4(0,0,0,0); }

    #pragma unroll 4
    for (int k = 0; k < IN_C; k++) {
        float4 w0 = Wes4[k * 16 + 2 * g];
        float4 w1 = Wes4[k * 16 + 2 * g + 1];
        #pragma unroll
        for (int j = 0; j < 4; j++) {
            float v = Xs[(nb + 32 * j) * 129 + k];
            aA[j].x += v * w0.x; aA[j].y += v * w0.y; aA[j].z += v * w0.z; aA[j].w += v * w0.w;
            aB[j].x += v * w1.x; aB[j].y += v * w1.y; aB[j].z += v * w1.z; aB[j].w += v * w1.w;
        }
    }
    #pragma unroll
    for (int j = 0; j < 4; j++) {
        aA[j].x += beA.x; aA[j].y += beA.y; aA[j].z += beA.z; aA[j].w += beA.w;
        aB[j].x += beB.x; aB[j].y += beB.y; aB[j].z += beB.z; aB[j].w += beB.w;
        int gn = base + nb + 32 * j;
        if (gn < NN) { g_xh4[gn * 16 + 2 * g] = aA[j]; g_xh4[gn * 16 + 2 * g + 1] = aB[j]; }
    }

    __syncthreads();
    #pragma unroll
    for (int j = 0; j < 4; j++) {
        float* rr = Xs + (nb + 32 * j) * 129 + 8 * g;
        rr[0]=aA[j].x; rr[1]=aA[j].y; rr[2]=aA[j].z; rr[3]=aA[j].w;
        rr[4]=aB[j].x; rr[5]=aB[j].y; rr[6]=aB[j].z; rr[7]=aB[j].w;
    }
    __syncthreads();

    float4 cA[4], cB[4];
    #pragma unroll
    for (int j = 0; j < 4; j++) { cA[j] = make_float4(0,0,0,0); cB[j] = make_float4(0,0,0,0); }
    #pragma unroll 4
    for (int k = 0; k < HH; k++) {
        float4 w0 = Uts4[k * 16 + 2 * g];
        float4 w1 = Uts4[k * 16 + 2 * g + 1];
        #pragma unroll
        for (int j = 0; j < 4; j++) {
            float v = Xs[(nb + 32 * j) * 129 + k];
            cA[j].x += v * w0.x; cA[j].y += v * w0.y; cA[j].z += v * w0.z; cA[j].w += v * w0.w;
            cB[j].x += v * w1.x; cB[j].y += v * w1.y; cB[j].z += v * w1.z; cB[j].w += v * w1.w;
        }
    }
    float4 z4 = make_float4(0,0,0,0);
    #pragma unroll
    for (int j = 0; j < 4; j++) {
        int gn = base + nb + 32 * j;
        if (gn >= NN) continue;
        float nfv = nf[gn];
        float deg = 1.0f / nfv;
        if (isinf(deg)) deg = 0.0f;
        float4 xuA, xuB, hA, hB;
        xuA.x = deg * (cA[j].x + bUA.x); xuA.y = deg * (cA[j].y + bUA.y);
        xuA.z = deg * (cA[j].z + bUA.z); xuA.w = deg * (cA[j].w + bUA.w);
        xuB.x = deg * (cB[j].x + bUB.x); xuB.y = deg * (cB[j].y + bUB.y);
        xuB.z = deg * (cB[j].z + bUB.z); xuB.w = deg * (cB[j].w + bUB.w);
        hA.x = nfv * xuA.x; hA.y = nfv * xuA.y; hA.z = nfv * xuA.z; hA.w = nfv * xuA.w;
        hB.x = nfv * xuB.x; hB.y = nfv * xuB.y; hB.z = nfv * xuB.z; hB.w = nfv * xuB.w;
        g_xU4[gn * 16 + 2 * g] = xuA; g_xU4[gn * 16 + 2 * g + 1] = xuB;
        g_h4 [gn * 16 + 2 * g] = hA;  g_h4 [gn * 16 + 2 * g + 1] = hB;
        g_z4 [gn * 16 + 2 * g] = z4;  g_z4 [gn * 16 + 2 * g + 1] = z4;
        g_a4 [gn * 16 + 2 * g] = z4;  g_a4 [gn * 16 + 2 * g + 1] = z4;
    }
}

// ---------------------------------------------------------------------------
// Edge: 8-lane groups, 2 x float4 = 8 channels per lane.
// m = LN(tanh(h[r]-h[c])); a[r] += m*nf[r]; a[c] -= m*nf[c]
// ---------------------------------------------------------------------------
__global__ __launch_bounds__(256) void k_edge(const float* __restrict__ nf,
                                              const float* __restrict__ gamma,
                                              const float* __restrict__ beta) {
    int tid = blockIdx.x * blockDim.x + threadIdx.x;
    int l = threadIdx.x & 7;
    int grp = tid >> 3;
    int ngrp = (gridDim.x * blockDim.x) >> 3;
    unsigned qmask = 0xFFu << (threadIdx.x & 24);

    const float4 gmA = ((const float4*)gamma)[2 * l];
    const float4 gmB = ((const float4*)gamma)[2 * l + 1];
    const float4 btA = ((const float4*)beta)[2 * l];
    const float4 btB = ((const float4*)beta)[2 * l + 1];

    for (int e = grp; e < EE; e += ngrp) {
        int r  = g_row[e];
        int cn = g_col[e];
        float nfr = __ldg(nf + r);
        float nfc = __ldg(nf + cn);
        const float4 hrA = __ldg(&g_h4[r  * 16 + 2 * l]);
        const float4 hrB = __ldg(&g_h4[r  * 16 + 2 * l + 1]);
        const float4 hcA = __ldg(&g_h4[cn * 16 + 2 * l]);
        const float4 hcB = __ldg(&g_h4[cn * 16 + 2 * l + 1]);

        float t0 = htanh(hrA.x - hcA.x);
        float t1 = htanh(hrA.y - hcA.y);
        float t2 = htanh(hrA.z - hcA.z);
        float t3 = htanh(hrA.w - hcA.w);
        float t4 = htanh(hrB.x - hcB.x);
        float t5 = htanh(hrB.y - hcB.y);
        float t6 = htanh(hrB.z - hcB.z);
        float t7 = htanh(hrB.w - hcB.w);

        float s  = (t0 + t1) + (t2 + t3) + ((t4 + t5) + (t6 + t7));
        float s2 = (t0*t0 + t1*t1) + (t2*t2 + t3*t3) + ((t4*t4 + t5*t5) + (t6*t6 + t7*t7));
        #pragma unroll
        for (int m = 4; m; m >>= 1) {
            s  += __shfl_xor_sync(qmask, s,  m);
            s2 += __shfl_xor_sync(qmask, s2, m);
        }
        float mean = s * (1.0f / 64.0f);
        float var  = s2 * (1.0f / 64.0f) - mean * mean;
        float rstd = rsqrtf(var + LN_EPS);

        float m0 = gmA.x * ((t0 - mean) * rstd) + btA.x;
        float m1 = gmA.y * ((t1 - mean) * rstd) + btA.y;
        float m2 = gmA.z * ((t2 - mean) * rstd) + btA.z;
        float m3 = gmA.w * ((t3 - mean) * rstd) + btA.w;
        float m4 = gmB.x * ((t4 - mean) * rstd) + btB.x;
        float m5 = gmB.y * ((t5 - mean) * rstd) + btB.y;
        float m6 = gmB.z * ((t6 - mean) * rstd) + btB.z;
        float m7 = gmB.w * ((t7 - mean) * rstd) + btB.w;

        float* arA = (float*)(g_a4 + r  * 16 + 2 * l);
        float* acA = (float*)(g_a4 + cn * 16 + 2 * l);
        float nnc = -nfc;
        asm volatile("red.global.add.v4.f32 [%0], {%1,%2,%3,%4};"
                     :: "l"(arA), "f"(m0*nfr), "f"(m1*nfr), "f"(m2*nfr), "f"(m3*nfr) : "memory");
        asm volatile("red.global.add.v4.f32 [%0], {%1,%2,%3,%4};"
                     :: "l"(arA + 4), "f"(m4*nfr), "f"(m5*nfr), "f"(m6*nfr), "f"(m7*nfr) : "memory");
        asm volatile("red.global.add.v4.f32 [%0], {%1,%2,%3,%4};"
                     :: "l"(acA), "f"(m0*nnc), "f"(m1*nnc), "f"(m2*nnc), "f"(m3*nnc) : "memory");
        asm volatile("red.global.add.v4.f32 [%0], {%1,%2,%3,%4};"
                     :: "l"(acA + 4), "f"(m4*nnc), "f"(m5*nnc), "f"(m6*nnc), "f"(m7*nnc) : "memory");
    }
}

// ---------------------------------------------------------------------------
// Fused step: t = a@W ; z = -ALPHA*t + (1-ALPHA)*z ; h = nf*(z@W^T + xU) ; a = 0
// ---------------------------------------------------------------------------
__global__ __launch_bounds__(256) void k_fused(const float* __restrict__ W,
                                               const float* __restrict__ nf,
                                               int compute_h) {
    extern __shared__ float sm[];
    float* As  = sm;               // 128 * 65
    float* Ws  = sm + 128 * 65;    // 64 * 64
    float* Wts = Ws + HH * HH;     // 64 * 64

    int tid = threadIdx.x;
    int g = tid & 7, nb = tid >> 3;
    int base = blockIdx.x * 128;

    for (int idx = tid; idx < 128 * HH; idx += 256) {
        int n = idx >> 6, c = idx & 63;
        As[n * 65 + c] = (base + n < NN) ? g_a[(base + n) * HH + c] : 0.0f;
    }
    for (int idx = tid; idx < HH * HH; idx += 256) { Ws[idx] = W[idx]; Wts[idx] = g_WT[idx]; }
    __syncthreads();

    const float4* Ws4  = (const float4*)Ws;
    const float4* Wts4 = (const float4*)Wts;

    float4 tA[4], tB[4];
    #pragma unroll
    for (int j = 0; j < 4; j++) { tA[j] = make_float4(0,0,0,0); tB[j] = make_float4(0,0,0,0); }

    #pragma unroll 4
    for (int k = 0; k < HH; k++) {
        float4 w0 = Ws4[k * 16 + 2 * g];
        float4 w1 = Ws4[k * 16 + 2 * g + 1];
        #pragma unroll
        for (int j = 0; j < 4; j++) {
            float v = As[(nb + 32 * j) * 65 + k];
            tA[j].x += v * w0.x; tA[j].y += v * w0.y; tA[j].z += v * w0.z; tA[j].w += v * w0.w;
            tB[j].x += v * w1.x; tB[j].y += v * w1.y; tB[j].z += v * w1.z; tB[j].w += v * w1.w;
        }
    }

    float4 znA[4], znB[4];
    #pragma unroll
    for (int j = 0; j < 4; j++) {
        int gn = base + nb + 32 * j;
        if (gn >= NN) { znA[j] = make_float4(0,0,0,0); znB[j] = make_float4(0,0,0,0); continue; }
        float4 zA = g_z4[gn * 16 + 2 * g], zB = g_z4[gn * 16 + 2 * g + 1];
        znA[j].x = -ALPHA * tA[j].x + (1.0f - ALPHA) * zA.x;
        znA[j].y = -ALPHA * tA[j].y + (1.0f - ALPHA) * zA.y;
        znA[j].z = -ALPHA * tA[j].z + (1.0f - ALPHA) * zA.z;
        znA[j].w = -ALPHA * tA[j].w + (1.0f - ALPHA) * zA.w;
        znB[j].x = -ALPHA * tB[j].x + (1.0f - ALPHA) * zB.x;
        znB[j].y = -ALPHA * tB[j].y + (1.0f - ALPHA) * zB.y;
        znB[j].z = -ALPHA * tB[j].z + (1.0f - ALPHA) * zB.z;
        znB[j].w = -ALPHA * tB[j].w + (1.0f - ALPHA) * zB.w;
        g_z4[gn * 16 + 2 * g] = znA[j];
        g_z4[gn * 16 + 2 * g + 1] = znB[j];
    }

    __syncthreads();
    #pragma unroll
    for (int j = 0; j < 4; j++) {
        float* rr = As + (nb + 32 * j) * 65 + 8 * g;
        rr[0]=znA[j].x; rr[1]=znA[j].y; rr[2]=znA[j].z; rr[3]=znA[j].w;
        rr[4]=znB[j].x; rr[5]=znB[j].y; rr[6]=znB[j].z; rr[7]=znB[j].w;
    }
    __syncthreads();

    if (compute_h) {
        #pragma unroll
        for (int j = 0; j < 4; j++) { tA[j] = make_float4(0,0,0,0); tB[j] = make_float4(0,0,0,0); }
        #pragma unroll 4
        for (int k = 0; k < HH; k++) {
            float4 w0 = Wts4[k * 16 + 2 * g];
            float4 w1 = Wts4[k * 16 + 2 * g + 1];
            #pragma unroll
            for (int j = 0; j < 4; j++) {
                float v = As[(nb + 32 * j) * 65 + k];
                tA[j].x += v * w0.x; tA[j].y += v * w0.y; tA[j].z += v * w0.z; tA[j].w += v * w0.w;
                tB[j].x += v * w1.x; tB[j].y += v * w1.y; tB[j].z += v * w1.z; tB[j].w += v * w1.w;
            }
        }
        #pragma unroll
        for (int j = 0; j < 4; j++) {
            int gn = base + nb + 32 * j;
            if (gn >= NN) continue;
            float nfv = nf[gn];
            float4 xuA = g_xU4[gn * 16 + 2 * g], xuB = g_xU4[gn * 16 + 2 * g + 1];
            float4 hA, hB;
            hA.x = nfv * (tA[j].x + xuA.x); hA.y = nfv * (tA[j].y + xuA.y);
            hA.z = nfv * (tA[j].z + xuA.z); hA.w = nfv * (tA[j].w + xuA.w);
            hB.x = nfv * (tB[j].x + xuB.x); hB.y = nfv * (tB[j].y + xuB.y);
            hB.z = nfv * (tB[j].z + xuB.z); hB.w = nfv * (tB[j].w + xuB.w);
            g_h4[gn * 16 + 2 * g] = hA;
            g_h4[gn * 16 + 2 * g + 1] = hB;
        }
    }

    float4 zero4 = make_float4(0,0,0,0);
    #pragma unroll
    for (int j = 0; j < 4; j++) {
        int gn = base + nb + 32 * j;
        if (gn >= NN) continue;
        g_a4[gn * 16 + 2 * g] = zero4;
        g_a4[gn * 16 + 2 * g + 1] = zero4;
    }
}

// ---------------------------------------------------------------------------
// Out: out = (nf*z + xh) @ Wlast^T + blast  (Wl padded to 64 cols, c>=40 = 0)
// 128 nodes/block, thread: 4 nodes x 8 channels; only g<5 writes.
// dyn smem: Sv[128*65] | Wls[64*64]
// ---------------------------------------------------------------------------
__global__ __launch_bounds__(256) void k_out(const float* __restrict__ nf,
                                             const float* __restrict__ bl,
                                             float* __restrict__ out) {
    extern __shared__ float sm[];
    float* Sv  = sm;               // 128 * 65
    float* Wls = sm + 128 * 65;    // 64 * 64

    int tid = threadIdx.x;
    int g = tid & 7, nb = tid >> 3;
    int base = blockIdx.x * 128;

    for (int idx = tid; idx < 128 * HH; idx += 256) {
        int n = idx >> 6, c = idx & 63;
        int gn = base + n;
        Sv[n * 65 + c] = (gn < NN) ? (nf[gn] * g_z[gn * HH + c] + g_xh[gn * HH + c]) : 0.0f;
    }
    for (int idx = tid; idx < HH * HH; idx += 256) Wls[idx] = g_WlT[idx];
    __syncthreads();

    const float4* Wls4 = (const float4*)Wls;
    float4 tA[4], tB[4];
    #pragma unroll
    for (int j = 0; j < 4; j++) { tA[j] = make_float4(0,0,0,0); tB[j] = make_float4(0,0,0,0); }

    #pragma unroll 4
    for (int k = 0; k < HH; k++) {
        float4 w0 = Wls4[k * 16 + 2 * g];
        float4 w1 = Wls4[k * 16 + 2 * g + 1];
        #pragma unroll
        for (int j = 0; j < 4; j++) {
            float v = Sv[(nb + 32 * j) * 65 + k];
            tA[j].x += v * w0.x; tA[j].y += v * w0.y; tA[j].z += v * w0.z; tA[j].w += v * w0.w;
            tB[j].x += v * w1.x; tB[j].y += v * w1.y; tB[j].z += v * w1.z; tB[j].w += v * w1.w;
        }
    }
    if (g < 5) {
        float4 blA = ((const float4*)bl)[2 * g];
        float4 blB = (g < 4) ? ((const float4*)bl)[2 * g + 1] : ((const float4*)bl)[9];
        #pragma unroll
        for (int j = 0; j < 4; j++) {
            int gn = base + nb + 32 * j;
            if (gn >= NN) continue;
            float4 oA, oB;
            oA.x = tA[j].x + blA.x; oA.y = tA[j].y + blA.y; oA.z = tA[j].z + blA.z; oA.w = tA[j].w + blA.w;
            oB.x = tB[j].x + blB.x; oB.y = tB[j].y + blB.y; oB.z = tB[j].z + blB.z; oB.w = tB[j].w + blB.w;
            float4* po = (float4*)(out + gn * OUT_C + 8 * g);
            po[0] = oA;
            po[1] = oB;
        }
    }
}

// ---------------------------------------------------------------------------
extern "C" void kernel_launch(void* const* d_in, const int* in_sizes, int n_in,
                              void* d_out, int out_size) {
    const float* x     = (const float*)d_in[0];
    const int*   eiRaw = (const int*)d_in[1];
    const float* nf    = (const float*)d_in[2];
    const float* We    = (const float*)d_in[3];
    const float* be    = (const float*)d_in[4];
    const float* W     = (const float*)d_in[5];
    const float* U     = (const float*)d_in[6];
    const float* bU    = (const float*)d_in[7];
    const float* gamma = (const float*)d_in[8];
    const float* beta  = (const float*)d_in[9];
    const float* Wl    = (const float*)d_in[10];
    const float* bl    = (const float*)d_in[11];
    float* out = (float*)d_out;

    size_t front_smem = (size_t)(128 * 129 + IN_C * HH + HH * HH) * sizeof(float);
    size_t fused_smem = (size_t)(128 * 65 + 2 * HH * HH) * sizeof(float);
    size_t out_smem   = (size_t)(128 * 65 + HH * HH) * sizeof(float);
    cudaFuncSetAttribute(k_front, cudaFuncAttributeMaxDynamicSharedMemorySize, (int)front_smem);
    cudaFuncSetAttribute(k_fused, cudaFuncAttributeMaxDynamicSharedMemorySize, (int)fused_smem);
    cudaFuncSetAttribute(k_out,   cudaFuncAttributeMaxDynamicSharedMemorySize, (int)out_smem);

    k_probe<<<1, 32>>>(eiRaw);
    k_convert<<<(EE + 255) / 256, 256>>>(eiRaw);
    k_prep<<<(IN_C * HH + 255) / 256, 256>>>(We, U, W, Wl);

    int nodeBlocks = (NN + 127) / 128;
    k_front<<<nodeBlocks, 256, front_smem>>>(x, be, bU, nf);

    for (int s = 0; s < 4; s++) {
        k_edge<<<1184, 256>>>(nf, gamma, beta);
        k_fused<<<nodeBlocks, 256, fused_smem>>>(W, nf, s < 3 ? 1 : 0);
    }

    k_out<<<nodeBlocks, 256, out_smem>>>(nf, bl, out);
}

// round 5
// speedup vs baseline: 1.3037x; 1.3037x over previous
#include <cuda_runtime.h>
#include <cstdint>

#define NN 50000
#define EE 1600000
#define IN_C 128
#define HH 64
#define OUT_C 40
#define ALPHA 0.8f
#define LN_EPS 1e-5f

// Scratch (device globals; 16B-aligned via float4)
__device__ float4 g_xh4[NN * 16];
__device__ float4 g_xU4[NN * 16];
__device__ float4 g_h4 [NN * 16];
__device__ float4 g_a4 [NN * 16];
__device__ float4 g_z4 [NN * 16];
__device__ int    g_row[EE];
__device__ int    g_col[EE];
__device__ int    g_is64;
// pre-transposed weights
__device__ float  g_WeT[IN_C * HH];   // [k][c] = We[c][k]
__device__ float  g_UT [HH * HH];     // [k][c] = U[c][k]
__device__ float  g_WT [HH * HH];     // [k][c] = W[c][k]
__device__ float  g_WlT[HH * HH];     // [k][c] = Wl[c][k], zero-padded c>=40

#define g_xh ((float*)g_xh4)
#define g_a  ((float*)g_a4)
#define g_z  ((float*)g_z4)

__device__ __forceinline__ float htanh(float x) {
    float y;
    asm("tanh.approx.f32 %0, %1;" : "=f"(y) : "f"(x));
    return y;
}

// ---------------------------------------------------------------------------
__global__ void k_probe(const int* __restrict__ ei_raw) {
    if (threadIdx.x == 0 && blockIdx.x == 0) {
        int allzero = 1;
        #pragma unroll
        for (int i = 1; i < 128; i += 2) allzero &= (ei_raw[i] == 0);
        g_is64 = allzero;
    }
}

__global__ __launch_bounds__(256) void k_convert(const int* __restrict__ ei_raw) {
    int e = blockIdx.x * blockDim.x + threadIdx.x;
    if (e >= EE) return;
    if (g_is64) {
        const long long* p = (const long long*)ei_raw;
        g_row[e] = (int)p[e];
        g_col[e] = (int)p[EE + e];
    } else {
        g_row[e] = ei_raw[e];
        g_col[e] = ei_raw[EE + e];
    }
}

// ---------------------------------------------------------------------------
__global__ __launch_bounds__(256) void k_prep(const float* __restrict__ We,
                                              const float* __restrict__ U,
                                              const float* __restrict__ W,
                                              const float* __restrict__ Wl) {
    int idx = blockIdx.x * blockDim.x + threadIdx.x;
    if (idx < IN_C * HH) {
        int k = idx >> 6, c = idx & 63;
        g_WeT[idx] = We[c * IN_C + k];
    }
    if (idx < HH * HH) {
        int k = idx >> 6, c = idx & 63;
        g_UT[idx]  = U[c * HH + k];
        g_WT[idx]  = W[c * HH + k];
        g_WlT[idx] = (c < OUT_C) ? Wl[c * HH + k] : 0.0f;
    }
}

// ---------------------------------------------------------------------------
// Front: xh = x@We^T + be ; xU = deg*(xh@U^T + bU) ; h0 = nf*xU ; z=0 ; a=0
// 128 nodes/block, 256 threads; thread: 4 nodes x 8 channels.
// ---------------------------------------------------------------------------
__global__ __launch_bounds__(256) void k_front(const float* __restrict__ x,
                                               const float* __restrict__ be,
                                               const float* __restrict__ bU,
                                               const float* __restrict__ nf) {
    extern __shared__ float sm[];
    float* Xs  = sm;                 // 128 * 129
    float* Wes = sm + 128 * 129;     // 128 * 64
    float* Uts = Wes + IN_C * HH;    // 64 * 64

    int tid = threadIdx.x;
    int g = tid & 7, nb = tid >> 3;
    int base = blockIdx.x * 128;

    for (int idx = tid; idx < 128 * IN_C; idx += 256) {
        int n = idx >> 7, k = idx & 127;
        Xs[n * 129 + k] = (base + n < NN) ? x[(base + n) * IN_C + k] : 0.0f;
    }
    for (int idx = tid; idx < IN_C * HH; idx += 256) Wes[idx] = g_WeT[idx];
    for (int idx = tid; idx < HH * HH; idx += 256)  Uts[idx] = g_UT[idx];
    __syncthreads();

    const float4* Wes4 = (const float4*)Wes;
    const float4* Uts4 = (const float4*)Uts;
    float4 beA = ((const float4*)be)[2 * g], beB = ((const float4*)be)[2 * g + 1];
    float4 bUA = ((const float4*)bU)[2 * g], bUB = ((const float4*)bU)[2 * g + 1];

    float4 aA[4], aB[4];
    #pragma unroll
    for (int j = 0; j < 4; j++) { aA[j] = make_float4(0,0,0,0); aB[j] = make_float4(0,0,0,0); }

    #pragma unroll 4
    for (int k = 0; k < IN_C; k++) {
        float4 w0 = Wes4[k * 16 + 2 * g];
        float4 w1 = Wes4[k * 16 + 2 * g + 1];
        #pragma unroll
        for (int j = 0; j < 4; j++) {
            float v = Xs[(nb + 32 * j) * 129 + k];
            aA[j].x += v * w0.x; aA[j].y += v * w0.y; aA[j].z += v * w0.z; aA[j].w += v * w0.w;
            aB[j].x += v * w1.x; aB[j].y += v * w1.y; aB[j].z += v * w1.z; aB[j].w += v * w1.w;
        }
    }
    #pragma unroll
    for (int j = 0; j < 4; j++) {
        aA[j].x += beA.x; aA[j].y += beA.y; aA[j].z += beA.z; aA[j].w += beA.w;
        aB[j].x += beB.x; aB[j].y += beB.y; aB[j].z += beB.z; aB[j].w += beB.w;
        int gn = base + nb + 32 * j;
        if (gn < NN) { g_xh4[gn * 16 + 2 * g] = aA[j]; g_xh4[gn * 16 + 2 * g + 1] = aB[j]; }
    }

    __syncthreads();
    #pragma unroll
    for (int j = 0; j < 4; j++) {
        float* rr = Xs + (nb + 32 * j) * 129 + 8 * g;
        rr[0]=aA[j].x; rr[1]=aA[j].y; rr[2]=aA[j].z; rr[3]=aA[j].w;
        rr[4]=aB[j].x; rr[5]=aB[j].y; rr[6]=aB[j].z; rr[7]=aB[j].w;
    }
    __syncthreads();

    float4 cA[4], cB[4];
    #pragma unroll
    for (int j = 0; j < 4; j++) { cA[j] = make_float4(0,0,0,0); cB[j] = make_float4(0,0,0,0); }
    #pragma unroll 4
    for (int k = 0; k < HH; k++) {
        float4 w0 = Uts4[k * 16 + 2 * g];
        float4 w1 = Uts4[k * 16 + 2 * g + 1];
        #pragma unroll
        for (int j = 0; j < 4; j++) {
            float v = Xs[(nb + 32 * j) * 129 + k];
            cA[j].x += v * w0.x; cA[j].y += v * w0.y; cA[j].z += v * w0.z; cA[j].w += v * w0.w;
            cB[j].x += v * w1.x; cB[j].y += v * w1.y; cB[j].z += v * w1.z; cB[j].w += v * w1.w;
        }
    }
    float4 z4 = make_float4(0,0,0,0);
    #pragma unroll
    for (int j = 0; j < 4; j++) {
        int gn = base + nb + 32 * j;
        if (gn >= NN) continue;
        float nfv = nf[gn];
        float deg = 1.0f / nfv;
        if (isinf(deg)) deg = 0.0f;
        float4 xuA, xuB, hA, hB;
        xuA.x = deg * (cA[j].x + bUA.x); xuA.y = deg * (cA[j].y + bUA.y);
        xuA.z = deg * (cA[j].z + bUA.z); xuA.w = deg * (cA[j].w + bUA.w);
        xuB.x = deg * (cB[j].x + bUB.x); xuB.y = deg * (cB[j].y + bUB.y);
        xuB.z = deg * (cB[j].z + bUB.z); xuB.w = deg * (cB[j].w + bUB.w);
        hA.x = nfv * xuA.x; hA.y = nfv * xuA.y; hA.z = nfv * xuA.z; hA.w = nfv * xuA.w;
        hB.x = nfv * xuB.x; hB.y = nfv * xuB.y; hB.z = nfv * xuB.z; hB.w = nfv * xuB.w;
        g_xU4[gn * 16 + 2 * g] = xuA; g_xU4[gn * 16 + 2 * g + 1] = xuB;
        g_h4 [gn * 16 + 2 * g] = hA;  g_h4 [gn * 16 + 2 * g + 1] = hB;
        g_z4 [gn * 16 + 2 * g] = z4;  g_z4 [gn * 16 + 2 * g + 1] = z4;
        g_a4 [gn * 16 + 2 * g] = z4;  g_a4 [gn * 16 + 2 * g + 1] = z4;
    }
}

// ---------------------------------------------------------------------------
// Edge: 16-lane groups, 1 float4 per lane (dense 256B per endpoint).
// m = LN(tanh(h[r]-h[c])); a[r] += m*nf[r]; a[c] -= m*nf[c]
// ---------------------------------------------------------------------------
__global__ __launch_bounds__(256) void k_edge(const float* __restrict__ nf,
                                              const float* __restrict__ gamma,
                                              const float* __restrict__ beta) {
    int tid = blockIdx.x * blockDim.x + threadIdx.x;
    int l = threadIdx.x & 15;
    int hw = tid >> 4;
    int nhw = (gridDim.x * blockDim.x) >> 4;
    unsigned hmask = 0xFFFFu << (threadIdx.x & 16);

    const float4 gm = *(const float4*)(gamma + 4 * l);
    const float4 bt = *(const float4*)(beta + 4 * l);

    for (int e = hw; e < EE; e += nhw) {
        int r  = g_row[e];
        int cn = g_col[e];
        const float4 hr = __ldg(&g_h4[r  * 16 + l]);
        const float4 hc = __ldg(&g_h4[cn * 16 + l]);

        float t0 = htanh(hr.x - hc.x);
        float t1 = htanh(hr.y - hc.y);
        float t2 = htanh(hr.z - hc.z);
        float t3 = htanh(hr.w - hc.w);

        float s  = t0 + t1 + t2 + t3;
        float s2 = t0 * t0 + t1 * t1 + t2 * t2 + t3 * t3;
        #pragma unroll
        for (int m = 8; m; m >>= 1) {
            s  += __shfl_xor_sync(hmask, s,  m);
            s2 += __shfl_xor_sync(hmask, s2, m);
        }
        float mean = s * (1.0f / 64.0f);
        float var  = s2 * (1.0f / 64.0f) - mean * mean;
        float rstd = rsqrtf(var + LN_EPS);

        float m0 = gm.x * ((t0 - mean) * rstd) + bt.x;
        float m1 = gm.y * ((t1 - mean) * rstd) + bt.y;
        float m2 = gm.z * ((t2 - mean) * rstd) + bt.z;
        float m3 = gm.w * ((t3 - mean) * rstd) + bt.w;

        float nfr = __ldg(nf + r);
        float nfc = -__ldg(nf + cn);
        float* ar = (float*)(g_a4 + r  * 16 + l);
        float* ac = (float*)(g_a4 + cn * 16 + l);
        asm volatile("red.global.add.v4.f32 [%0], {%1,%2,%3,%4};"
                     :: "l"(ar), "f"(m0 * nfr), "f"(m1 * nfr), "f"(m2 * nfr), "f"(m3 * nfr)
                     : "memory");
        asm volatile("red.global.add.v4.f32 [%0], {%1,%2,%3,%4};"
                     :: "l"(ac), "f"(m0 * nfc), "f"(m1 * nfc), "f"(m2 * nfc), "f"(m3 * nfc)
                     : "memory");
    }
}

// ---------------------------------------------------------------------------
// Fused step: t = a@W ; z = -ALPHA*t + (1-ALPHA)*z ; h = nf*(z@W^T + xU) ; a = 0
// ---------------------------------------------------------------------------
__global__ __launch_bounds__(256) void k_fused(const float* __restrict__ W,
                                               const float* __restrict__ nf,
                                               int compute_h) {
    extern __shared__ float sm[];
    float* As  = sm;               // 128 * 65
    float* Ws  = sm + 128 * 65;    // 64 * 64
    float* Wts = Ws + HH * HH;     // 64 * 64

    int tid = threadIdx.x;
    int g = tid & 7, nb = tid >> 3;
    int base = blockIdx.x * 128;

    for (int idx = tid; idx < 128 * HH; idx += 256) {
        int n = idx >> 6, c = idx & 63;
        As[n * 65 + c] = (base + n < NN) ? g_a[(base + n) * HH + c] : 0.0f;
    }
    for (int idx = tid; idx < HH * HH; idx += 256) { Ws[idx] = W[idx]; Wts[idx] = g_WT[idx]; }
    __syncthreads();

    const float4* Ws4  = (const float4*)Ws;
    const float4* Wts4 = (const float4*)Wts;

    float4 tA[4], tB[4];
    #pragma unroll
    for (int j = 0; j < 4; j++) { tA[j] = make_float4(0,0,0,0); tB[j] = make_float4(0,0,0,0); }

    #pragma unroll 4
    for (int k = 0; k < HH; k++) {
        float4 w0 = Ws4[k * 16 + 2 * g];
        float4 w1 = Ws4[k * 16 + 2 * g + 1];
        #pragma unroll
        for (int j = 0; j < 4; j++) {
            float v = As[(nb + 32 * j) * 65 + k];
            tA[j].x += v * w0.x; tA[j].y += v * w0.y; tA[j].z += v * w0.z; tA[j].w += v * w0.w;
            tB[j].x += v * w1.x; tB[j].y += v * w1.y; tB[j].z += v * w1.z; tB[j].w += v * w1.w;
        }
    }

    float4 znA[4], znB[4];
    #pragma unroll
    for (int j = 0; j < 4; j++) {
        int gn = base + nb + 32 * j;
        if (gn >= NN) { znA[j] = make_float4(0,0,0,0); znB[j] = make_float4(0,0,0,0); continue; }
        float4 zA = g_z4[gn * 16 + 2 * g], zB = g_z4[gn * 16 + 2 * g + 1];
        znA[j].x = -ALPHA * tA[j].x + (1.0f - ALPHA) * zA.x;
        znA[j].y = -ALPHA * tA[j].y + (1.0f - ALPHA) * zA.y;
        znA[j].z = -ALPHA * tA[j].z + (1.0f - ALPHA) * zA.z;
        znA[j].w = -ALPHA * tA[j].w + (1.0f - ALPHA) * zA.w;
        znB[j].x = -ALPHA * tB[j].x + (1.0f - ALPHA) * zB.x;
        znB[j].y = -ALPHA * tB[j].y + (1.0f - ALPHA) * zB.y;
        znB[j].z = -ALPHA * tB[j].z + (1.0f - ALPHA) * zB.z;
        znB[j].w = -ALPHA * tB[j].w + (1.0f - ALPHA) * zB.w;
        g_z4[gn * 16 + 2 * g] = znA[j];
        g_z4[gn * 16 + 2 * g + 1] = znB[j];
    }

    __syncthreads();
    #pragma unroll
    for (int j = 0; j < 4; j++) {
        float* rr = As + (nb + 32 * j) * 65 + 8 * g;
        rr[0]=znA[j].x; rr[1]=znA[j].y; rr[2]=znA[j].z; rr[3]=znA[j].w;
        rr[4]=znB[j].x; rr[5]=znB[j].y; rr[6]=znB[j].z; rr[7]=znB[j].w;
    }
    __syncthreads();

    if (compute_h) {
        #pragma unroll
        for (int j = 0; j < 4; j++) { tA[j] = make_float4(0,0,0,0); tB[j] = make_float4(0,0,0,0); }
        #pragma unroll 4
        for (int k = 0; k < HH; k++) {
            float4 w0 = Wts4[k * 16 + 2 * g];
            float4 w1 = Wts4[k * 16 + 2 * g + 1];
            #pragma unroll
            for (int j = 0; j < 4; j++) {
                float v = As[(nb + 32 * j) * 65 + k];
                tA[j].x += v * w0.x; tA[j].y += v * w0.y; tA[j].z += v * w0.z; tA[j].w += v * w0.w;
                tB[j].x += v * w1.x; tB[j].y += v * w1.y; tB[j].z += v * w1.z; tB[j].w += v * w1.w;
            }
        }
        #pragma unroll
        for (int j = 0; j < 4; j++) {
            int gn = base + nb + 32 * j;
            if (gn >= NN) continue;
            float nfv = nf[gn];
            float4 xuA = g_xU4[gn * 16 + 2 * g], xuB = g_xU4[gn * 16 + 2 * g + 1];
            float4 hA, hB;
            hA.x = nfv * (tA[j].x + xuA.x); hA.y = nfv * (tA[j].y + xuA.y);
            hA.z = nfv * (tA[j].z + xuA.z); hA.w = nfv * (tA[j].w + xuA.w);
            hB.x = nfv * (tB[j].x + xuB.x); hB.y = nfv * (tB[j].y + xuB.y);
            hB.z = nfv * (tB[j].z + xuB.z); hB.w = nfv * (tB[j].w + xuB.w);
            g_h4[gn * 16 + 2 * g] = hA;
            g_h4[gn * 16 + 2 * g + 1] = hB;
        }
    }

    float4 zero4 = make_float4(0,0,0,0);
    #pragma unroll
    for (int j = 0; j < 4; j++) {
        int gn = base + nb + 32 * j;
        if (gn >= NN) continue;
        g_a4[gn * 16 + 2 * g] = zero4;
        g_a4[gn * 16 + 2 * g + 1] = zero4;
    }
}

// ---------------------------------------------------------------------------
// Out: out = (nf*z + xh) @ Wlast^T + blast  (Wl padded to 64 cols, c>=40 = 0)
// ---------------------------------------------------------------------------
__global__ __launch_bounds__(256) void k_out(const float* __restrict__ nf,
                                             const float* __restrict__ bl,
                                             float* __restrict__ out) {
    extern __shared__ float sm[];
    float* Sv  = sm;               // 128 * 65
    float* Wls = sm + 128 * 65;    // 64 * 64

    int tid = threadIdx.x;
    int g = tid & 7, nb = tid >> 3;
    int base = blockIdx.x * 128;

    for (int idx = tid; idx < 128 * HH; idx += 256) {
        int n = idx >> 6, c = idx & 63;
        int gn = base + n;
        Sv[n * 65 + c] = (gn < NN) ? (nf[gn] * g_z[gn * HH + c] + g_xh[gn * HH + c]) : 0.0f;
    }
    for (int idx = tid; idx < HH * HH; idx += 256) Wls[idx] = g_WlT[idx];
    __syncthreads();

    const float4* Wls4 = (const float4*)Wls;
    float4 tA[4], tB[4];
    #pragma unroll
    for (int j = 0; j < 4; j++) { tA[j] = make_float4(0,0,0,0); tB[j] = make_float4(0,0,0,0); }

    #pragma unroll 4
    for (int k = 0; k < HH; k++) {
        float4 w0 = Wls4[k * 16 + 2 * g];
        float4 w1 = Wls4[k * 16 + 2 * g + 1];
        #pragma unroll
        for (int j = 0; j < 4; j++) {
            float v = Sv[(nb + 32 * j) * 65 + k];
            tA[j].x += v * w0.x; tA[j].y += v * w0.y; tA[j].z += v * w0.z; tA[j].w += v * w0.w;
            tB[j].x += v * w1.x; tB[j].y += v * w1.y; tB[j].z += v * w1.z; tB[j].w += v * w1.w;
        }
    }
    if (g < 5) {
        float4 blA = ((const float4*)bl)[2 * g];
        float4 blB = (g < 4) ? ((const float4*)bl)[2 * g + 1] : ((const float4*)bl)[9];
        #pragma unroll
        for (int j = 0; j < 4; j++) {
            int gn = base + nb + 32 * j;
            if (gn >= NN) continue;
            float4 oA, oB;
            oA.x = tA[j].x + blA.x; oA.y = tA[j].y + blA.y; oA.z = tA[j].z + blA.z; oA.w = tA[j].w + blA.w;
            oB.x = tB[j].x + blB.x; oB.y = tB[j].y + blB.y; oB.z = tB[j].z + blB.z; oB.w = tB[j].w + blB.w;
            float4* po = (float4*)(out + gn * OUT_C + 8 * g);
            po[0] = oA;
            po[1] = oB;
        }
    }
}

// ---------------------------------------------------------------------------
extern "C" void kernel_launch(void* const* d_in, const int* in_sizes, int n_in,
                              void* d_out, int out_size) {
    const float* x     = (const float*)d_in[0];
    const int*   eiRaw = (const int*)d_in[1];
    const float* nf    = (const float*)d_in[2];
    const float* We    = (const float*)d_in[3];
    const float* be    = (const float*)d_in[4];
    const float* W     = (const float*)d_in[5];
    const float* U     = (const float*)d_in[6];
    const float* bU    = (const float*)d_in[7];
    const float* gamma = (const float*)d_in[8];
    const float* beta  = (const float*)d_in[9];
    const float* Wl    = (const float*)d_in[10];
    const float* bl    = (const float*)d_in[11];
    float* out = (float*)d_out;

    size_t front_smem = (size_t)(128 * 129 + IN_C * HH + HH * HH) * sizeof(float);
    size_t fused_smem = (size_t)(128 * 65 + 2 * HH * HH) * sizeof(float);
    size_t out_smem   = (size_t)(128 * 65 + HH * HH) * sizeof(float);
    cudaFuncSetAttribute(k_front, cudaFuncAttributeMaxDynamicSharedMemorySize, (int)front_smem);
    cudaFuncSetAttribute(k_fused, cudaFuncAttributeMaxDynamicSharedMemorySize, (int)fused_smem);
    cudaFuncSetAttribute(k_out,   cudaFuncAttributeMaxDynamicSharedMemorySize, (int)out_smem);

    k_probe<<<1, 32>>>(eiRaw);
    k_convert<<<(EE + 255) / 256, 256>>>(eiRaw);
    k_prep<<<(IN_C * HH + 255) / 256, 256>>>(We, U, W, Wl);

    int nodeBlocks = (NN + 127) / 128;
    k_front<<<nodeBlocks, 256, front_smem>>>(x, be, bU, nf);

    for (int s = 0; s < 4; s++) {
        k_edge<<<1184, 256>>>(nf, gamma, beta);
        k_fused<<<nodeBlocks, 256, fused_smem>>>(W, nf, s < 3 ? 1 : 0);
    }

    k_out<<<nodeBlocks, 256, out_smem>>>(nf, bl, out);
}

// round 6
// speedup vs baseline: 1.3562x; 1.0402x over previous
#include <cuda_runtime.h>
#include <cstdint>

#define NN 50000
#define EE 1600000
#define IN_C 128
#define HH 64
#define OUT_C 40
#define ALPHA 0.8f
#define LN_EPS 1e-5f

#define XS_STRIDE 132
#define AS_STRIDE 68

// Scratch (device globals; 16B-aligned via float4)
__device__ float4 g_xh4[NN * 16];
__device__ float4 g_xU4[NN * 16];
__device__ float4 g_h4 [NN * 16];
__device__ float4 g_a4 [NN * 16];
__device__ float4 g_z4 [NN * 16];
__device__ int2   g_rc [EE];
__device__ int    g_is64;
// pre-transposed weights
__device__ float  g_WeT[IN_C * HH];   // [k][c] = We[c][k]
__device__ float  g_UT [HH * HH];     // [k][c] = U[c][k]
__device__ float  g_WT [HH * HH];     // [k][c] = W[c][k]
__device__ float  g_WlT[HH * HH];     // [k][c] = Wl[c][k], zero-padded c>=40

#define g_xh ((float*)g_xh4)
#define g_a  ((float*)g_a4)
#define g_z  ((float*)g_z4)

__device__ __forceinline__ float htanh(float x) {
    float y;
    asm("tanh.approx.f32 %0, %1;" : "=f"(y) : "f"(x));
    return y;
}

// ---------------------------------------------------------------------------
__global__ void k_probe(const int* __restrict__ ei_raw) {
    if (threadIdx.x == 0 && blockIdx.x == 0) {
        int allzero = 1;
        #pragma unroll
        for (int i = 1; i < 128; i += 2) allzero &= (ei_raw[i] == 0);
        g_is64 = allzero;
    }
}

__global__ __launch_bounds__(256) void k_convert(const int* __restrict__ ei_raw) {
    int e = blockIdx.x * blockDim.x + threadIdx.x;
    if (e >= EE) return;
    int r, c;
    if (g_is64) {
        const long long* p = (const long long*)ei_raw;
        r = (int)p[e];
        c = (int)p[EE + e];
    } else {
        r = ei_raw[e];
        c = ei_raw[EE + e];
    }
    g_rc[e] = make_int2(r, c);
}

// ---------------------------------------------------------------------------
__global__ __launch_bounds__(256) void k_prep(const float* __restrict__ We,
                                              const float* __restrict__ U,
                                              const float* __restrict__ W,
                                              const float* __restrict__ Wl) {
    int idx = blockIdx.x * blockDim.x + threadIdx.x;
    if (idx < IN_C * HH) {
        int k = idx >> 6, c = idx & 63;
        g_WeT[idx] = We[c * IN_C + k];
    }
    if (idx < HH * HH) {
        int k = idx >> 6, c = idx & 63;
        g_UT[idx]  = U[c * HH + k];
        g_WT[idx]  = W[c * HH + k];
        g_WlT[idx] = (c < OUT_C) ? Wl[c * HH + k] : 0.0f;
    }
}

// ---------------------------------------------------------------------------
// Front: xh = x@We^T + be ; xU = deg*(xh@U^T + bU) ; h0 = nf*xU ; z=0 ; a=0
// 128 nodes/block, 256 threads; thread: 4 nodes x 8 channels.
// dyn smem: Xs[128*132] | Wb[128*64]  (~98KB, 2 blocks/SM)
// ---------------------------------------------------------------------------
__global__ __launch_bounds__(256) void k_front(const float* __restrict__ x,
                                               const float* __restrict__ be,
                                               const float* __restrict__ bU,
                                               const float* __restrict__ nf) {
    extern __shared__ float sm[];
    float* Xs = sm;                   // 128 * 132
    float* Wb = sm + 128 * XS_STRIDE; // 128 * 64 (phase1: WeT; phase2: UT)

    int tid = threadIdx.x;
    int g = tid & 7, nb = tid >> 3;
    int base = blockIdx.x * 128;

    for (int idx = tid; idx < 128 * IN_C; idx += 256) {
        int n = idx >> 7, k = idx & 127;
        Xs[n * XS_STRIDE + k] = (base + n < NN) ? x[(base + n) * IN_C + k] : 0.0f;
    }
    for (int idx = tid; idx < IN_C * HH; idx += 256) Wb[idx] = g_WeT[idx];
    __syncthreads();

    const float4* Wb4 = (const float4*)Wb;
    float4 beA = ((const float4*)be)[2 * g], beB = ((const float4*)be)[2 * g + 1];
    float4 bUA = ((const float4*)bU)[2 * g], bUB = ((const float4*)bU)[2 * g + 1];

    float4 aA[4], aB[4];
    #pragma unroll
    for (int j = 0; j < 4; j++) { aA[j] = make_float4(0,0,0,0); aB[j] = make_float4(0,0,0,0); }

    #pragma unroll 2
    for (int k0 = 0; k0 < IN_C; k0 += 4) {
        float4 v[4];
        #pragma unroll
        for (int j = 0; j < 4; j++)
            v[j] = *(const float4*)(Xs + (nb + 32 * j) * XS_STRIDE + k0);
        #pragma unroll
        for (int kk = 0; kk < 4; kk++) {
            float4 w0 = Wb4[(k0 + kk) * 16 + 2 * g];
            float4 w1 = Wb4[(k0 + kk) * 16 + 2 * g + 1];
            #pragma unroll
            for (int j = 0; j < 4; j++) {
                float s = (kk == 0) ? v[j].x : (kk == 1) ? v[j].y : (kk == 2) ? v[j].z : v[j].w;
                aA[j].x += s * w0.x; aA[j].y += s * w0.y; aA[j].z += s * w0.z; aA[j].w += s * w0.w;
                aB[j].x += s * w1.x; aB[j].y += s * w1.y; aB[j].z += s * w1.z; aB[j].w += s * w1.w;
            }
        }
    }
    #pragma unroll
    for (int j = 0; j < 4; j++) {
        aA[j].x += beA.x; aA[j].y += beA.y; aA[j].z += beA.z; aA[j].w += beA.w;
        aB[j].x += beB.x; aB[j].y += beB.y; aB[j].z += beB.z; aB[j].w += beB.w;
        int gn = base + nb + 32 * j;
        if (gn < NN) { g_xh4[gn * 16 + 2 * g] = aA[j]; g_xh4[gn * 16 + 2 * g + 1] = aB[j]; }
    }

    __syncthreads();
    // stash xh into Xs; reload Wb with UT
    #pragma unroll
    for (int j = 0; j < 4; j++) {
        float* rr = Xs + (nb + 32 * j) * XS_STRIDE + 8 * g;
        rr[0]=aA[j].x; rr[1]=aA[j].y; rr[2]=aA[j].z; rr[3]=aA[j].w;
        rr[4]=aB[j].x; rr[5]=aB[j].y; rr[6]=aB[j].z; rr[7]=aB[j].w;
    }
    for (int idx = tid; idx < HH * HH; idx += 256) Wb[idx] = g_UT[idx];
    __syncthreads();

    float4 cA[4], cB[4];
    #pragma unroll
    for (int j = 0; j < 4; j++) { cA[j] = make_float4(0,0,0,0); cB[j] = make_float4(0,0,0,0); }
    #pragma unroll 2
    for (int k0 = 0; k0 < HH; k0 += 4) {
        float4 v[4];
        #pragma unroll
        for (int j = 0; j < 4; j++)
            v[j] = *(const float4*)(Xs + (nb + 32 * j) * XS_STRIDE + k0);
        #pragma unroll
        for (int kk = 0; kk < 4; kk++) {
            float4 w0 = Wb4[(k0 + kk) * 16 + 2 * g];
            float4 w1 = Wb4[(k0 + kk) * 16 + 2 * g + 1];
            #pragma unroll
            for (int j = 0; j < 4; j++) {
                float s = (kk == 0) ? v[j].x : (kk == 1) ? v[j].y : (kk == 2) ? v[j].z : v[j].w;
                cA[j].x += s * w0.x; cA[j].y += s * w0.y; cA[j].z += s * w0.z; cA[j].w += s * w0.w;
                cB[j].x += s * w1.x; cB[j].y += s * w1.y; cB[j].z += s * w1.z; cB[j].w += s * w1.w;
            }
        }
    }
    float4 z4 = make_float4(0,0,0,0);
    #pragma unroll
    for (int j = 0; j < 4; j++) {
        int gn = base + nb + 32 * j;
        if (gn >= NN) continue;
        float nfv = nf[gn];
        float deg = 1.0f / nfv;
        if (isinf(deg)) deg = 0.0f;
        float4 xuA, xuB, hA, hB;
        xuA.x = deg * (cA[j].x + bUA.x); xuA.y = deg * (cA[j].y + bUA.y);
        xuA.z = deg * (cA[j].z + bUA.z); xuA.w = deg * (cA[j].w + bUA.w);
        xuB.x = deg * (cB[j].x + bUB.x); xuB.y = deg * (cB[j].y + bUB.y);
        xuB.z = deg * (cB[j].z + bUB.z); xuB.w = deg * (cB[j].w + bUB.w);
        hA.x = nfv * xuA.x; hA.y = nfv * xuA.y; hA.z = nfv * xuA.z; hA.w = nfv * xuA.w;
        hB.x = nfv * xuB.x; hB.y = nfv * xuB.y; hB.z = nfv * xuB.z; hB.w = nfv * xuB.w;
        g_xU4[gn * 16 + 2 * g] = xuA; g_xU4[gn * 16 + 2 * g + 1] = xuB;
        g_h4 [gn * 16 + 2 * g] = hA;  g_h4 [gn * 16 + 2 * g + 1] = hB;
        g_z4 [gn * 16 + 2 * g] = z4;  g_z4 [gn * 16 + 2 * g + 1] = z4;
        g_a4 [gn * 16 + 2 * g] = z4;  g_a4 [gn * 16 + 2 * g + 1] = z4;
    }
}

// ---------------------------------------------------------------------------
// Edge: 16-lane groups, 1 float4/lane. nf factored out (applied in k_fused):
// m = LN(tanh(h[r]-h[c])); a[r] += m; a[c] -= m
// ---------------------------------------------------------------------------
__global__ __launch_bounds__(256) void k_edge(const float* __restrict__ gamma,
                                              const float* __restrict__ beta) {
    int tid = blockIdx.x * blockDim.x + threadIdx.x;
    int l = threadIdx.x & 15;
    int hw = tid >> 4;
    int nhw = (gridDim.x * blockDim.x) >> 4;
    unsigned hmask = 0xFFFFu << (threadIdx.x & 16);

    const float4 gm = *(const float4*)(gamma + 4 * l);
    const float4 bt = *(const float4*)(beta + 4 * l);

    for (int e = hw; e < EE; e += nhw) {
        int2 rc = __ldg(&g_rc[e]);
        const float4 hr = __ldg(&g_h4[rc.x * 16 + l]);
        const float4 hc = __ldg(&g_h4[rc.y * 16 + l]);

        float t0 = htanh(hr.x - hc.x);
        float t1 = htanh(hr.y - hc.y);
        float t2 = htanh(hr.z - hc.z);
        float t3 = htanh(hr.w - hc.w);

        float s  = t0 + t1 + t2 + t3;
        float s2 = t0 * t0 + t1 * t1 + t2 * t2 + t3 * t3;
        #pragma unroll
        for (int m = 8; m; m >>= 1) {
            s  += __shfl_xor_sync(hmask, s,  m);
            s2 += __shfl_xor_sync(hmask, s2, m);
        }
        float mean = s * (1.0f / 64.0f);
        float var  = s2 * (1.0f / 64.0f) - mean * mean;
        float rstd = rsqrtf(var + LN_EPS);

        float m0 = gm.x * ((t0 - mean) * rstd) + bt.x;
        float m1 = gm.y * ((t1 - mean) * rstd) + bt.y;
        float m2 = gm.z * ((t2 - mean) * rstd) + bt.z;
        float m3 = gm.w * ((t3 - mean) * rstd) + bt.w;

        float* ar = (float*)(g_a4 + rc.x * 16 + l);
        float* ac = (float*)(g_a4 + rc.y * 16 + l);
        asm volatile("red.global.add.v4.f32 [%0], {%1,%2,%3,%4};"
                     :: "l"(ar), "f"(m0), "f"(m1), "f"(m2), "f"(m3) : "memory");
        asm volatile("red.global.add.v4.f32 [%0], {%1,%2,%3,%4};"
                     :: "l"(ac), "f"(-m0), "f"(-m1), "f"(-m2), "f"(-m3) : "memory");
    }
}

// ---------------------------------------------------------------------------
// Fused step: a' = nf.*a_raw ; t = a'@W ; z = -ALPHA*t + (1-ALPHA)*z ;
//             h = nf*(z@W^T + xU) ; a_raw = 0
// dyn smem: As[128*68] | Ws[64*64] | Wts[64*64]  (66KB, 3 blocks/SM)
// ---------------------------------------------------------------------------
__global__ __launch_bounds__(256) void k_fused(const float* __restrict__ W,
                                               const float* __restrict__ nf,
                                               int compute_h) {
    extern __shared__ float sm[];
    float* As  = sm;                    // 128 * 68
    float* Ws  = sm + 128 * AS_STRIDE;  // 64 * 64
    float* Wts = Ws + HH * HH;          // 64 * 64

    int tid = threadIdx.x;
    int g = tid & 7, nb = tid >> 3;
    int base = blockIdx.x * 128;

    for (int idx = tid; idx < 128 * HH; idx += 256) {
        int n = idx >> 6, c = idx & 63;
        int gn = base + n;
        As[n * AS_STRIDE + c] = (gn < NN) ? nf[gn] * g_a[gn * HH + c] : 0.0f;
    }
    for (int idx = tid; idx < HH * HH; idx += 256) { Ws[idx] = W[idx]; Wts[idx] = g_WT[idx]; }
    __syncthreads();

    const float4* Ws4  = (const float4*)Ws;
    const float4* Wts4 = (const float4*)Wts;

    float4 tA[4], tB[4];
    #pragma unroll
    for (int j = 0; j < 4; j++) { tA[j] = make_float4(0,0,0,0); tB[j] = make_float4(0,0,0,0); }

    #pragma unroll 2
    for (int k0 = 0; k0 < HH; k0 += 4) {
        float4 v[4];
        #pragma unroll
        for (int j = 0; j < 4; j++)
            v[j] = *(const float4*)(As + (nb + 32 * j) * AS_STRIDE + k0);
        #pragma unroll
        for (int kk = 0; kk < 4; kk++) {
            float4 w0 = Ws4[(k0 + kk) * 16 + 2 * g];
            float4 w1 = Ws4[(k0 + kk) * 16 + 2 * g + 1];
            #pragma unroll
            for (int j = 0; j < 4; j++) {
                float s = (kk == 0) ? v[j].x : (kk == 1) ? v[j].y : (kk == 2) ? v[j].z : v[j].w;
                tA[j].x += s * w0.x; tA[j].y += s * w0.y; tA[j].z += s * w0.z; tA[j].w += s * w0.w;
                tB[j].x += s * w1.x; tB[j].y += s * w1.y; tB[j].z += s * w1.z; tB[j].w += s * w1.w;
            }
        }
    }

    float4 znA[4], znB[4];
    #pragma unroll
    for (int j = 0; j < 4; j++) {
        int gn = base + nb + 32 * j;
        if (gn >= NN) { znA[j] = make_float4(0,0,0,0); znB[j] = make_float4(0,0,0,0); continue; }
        float4 zA = g_z4[gn * 16 + 2 * g], zB = g_z4[gn * 16 + 2 * g + 1];
        znA[j].x = -ALPHA * tA[j].x + (1.0f - ALPHA) * zA.x;
        znA[j].y = -ALPHA * tA[j].y + (1.0f - ALPHA) * zA.y;
        znA[j].z = -ALPHA * tA[j].z + (1.0f - ALPHA) * zA.z;
        znA[j].w = -ALPHA * tA[j].w + (1.0f - ALPHA) * zA.w;
        znB[j].x = -ALPHA * tB[j].x + (1.0f - ALPHA) * zB.x;
        znB[j].y = -ALPHA * tB[j].y + (1.0f - ALPHA) * zB.y;
        znB[j].z = -ALPHA * tB[j].z + (1.0f - ALPHA) * zB.z;
        znB[j].w = -ALPHA * tB[j].w + (1.0f - ALPHA) * zB.w;
        g_z4[gn * 16 + 2 * g] = znA[j];
        g_z4[gn * 16 + 2 * g + 1] = znB[j];
    }

    __syncthreads();
    #pragma unroll
    for (int j = 0; j < 4; j++) {
        float* rr = As + (nb + 32 * j) * AS_STRIDE + 8 * g;
        rr[0]=znA[j].x; rr[1]=znA[j].y; rr[2]=znA[j].z; rr[3]=znA[j].w;
        rr[4]=znB[j].x; rr[5]=znB[j].y; rr[6]=znB[j].z; rr[7]=znB[j].w;
    }
    __syncthreads();

    if (compute_h) {
        #pragma unroll
        for (int j = 0; j < 4; j++) { tA[j] = make_float4(0,0,0,0); tB[j] = make_float4(0,0,0,0); }
        #pragma unroll 2
        for (int k0 = 0; k0 < HH; k0 += 4) {
            float4 v[4];
            #pragma unroll
            for (int j = 0; j < 4; j++)
                v[j] = *(const float4*)(As + (nb + 32 * j) * AS_STRIDE + k0);
            #pragma unroll
            for (int kk = 0; kk < 4; kk++) {
                float4 w0 = Wts4[(k0 + kk) * 16 + 2 * g];
                float4 w1 = Wts4[(k0 + kk) * 16 + 2 * g + 1];
                #pragma unroll
                for (int j = 0; j < 4; j++) {
                    float s = (kk == 0) ? v[j].x : (kk == 1) ? v[j].y : (kk == 2) ? v[j].z : v[j].w;
                    tA[j].x += s * w0.x; tA[j].y += s * w0.y; tA[j].z += s * w0.z; tA[j].w += s * w0.w;
                    tB[j].x += s * w1.x; tB[j].y += s * w1.y; tB[j].z += s * w1.z; tB[j].w += s * w1.w;
                }
            }
        }
        #pragma unroll
        for (int j = 0; j < 4; j++) {
            int gn = base + nb + 32 * j;
            if (gn >= NN) continue;
            float nfv = nf[gn];
            float4 xuA = g_xU4[gn * 16 + 2 * g], xuB = g_xU4[gn * 16 + 2 * g + 1];
            float4 hA, hB;
            hA.x = nfv * (tA[j].x + xuA.x); hA.y = nfv * (tA[j].y + xuA.y);
            hA.z = nfv * (tA[j].z + xuA.z); hA.w = nfv * (tA[j].w + xuA.w);
            hB.x = nfv * (tB[j].x + xuB.x); hB.y = nfv * (tB[j].y + xuB.y);
            hB.z = nfv * (tB[j].z + xuB.z); hB.w = nfv * (tB[j].w + xuB.w);
            g_h4[gn * 16 + 2 * g] = hA;
            g_h4[gn * 16 + 2 * g + 1] = hB;
        }
    }

    float4 zero4 = make_float4(0,0,0,0);
    #pragma unroll
    for (int j = 0; j < 4; j++) {
        int gn = base + nb + 32 * j;
        if (gn >= NN) continue;
        g_a4[gn * 16 + 2 * g] = zero4;
        g_a4[gn * 16 + 2 * g + 1] = zero4;
    }
}

// ---------------------------------------------------------------------------
// Out: out = (nf*z + xh) @ Wlast^T + blast  (Wl padded to 64 cols)
// dyn smem: Sv[128*68] | Wls[64*64]
// ---------------------------------------------------------------------------
__global__ __launch_bounds__(256) void k_out(const float* __restrict__ nf,
                                             const float* __restrict__ bl,
                                             float* __restrict__ out) {
    extern __shared__ float sm[];
    float* Sv  = sm;                    // 128 * 68
    float* Wls = sm + 128 * AS_STRIDE;  // 64 * 64

    int tid = threadIdx.x;
    int g = tid & 7, nb = tid >> 3;
    int base = blockIdx.x * 128;

    for (int idx = tid; idx < 128 * HH; idx += 256) {
        int n = idx >> 6, c = idx & 63;
        int gn = base + n;
        Sv[n * AS_STRIDE + c] = (gn < NN) ? (nf[gn] * g_z[gn * HH + c] + g_xh[gn * HH + c]) : 0.0f;
    }
    for (int idx = tid; idx < HH * HH; idx += 256) Wls[idx] = g_WlT[idx];
    __syncthreads();

    const float4* Wls4 = (const float4*)Wls;
    float4 tA[4], tB[4];
    #pragma unroll
    for (int j = 0; j < 4; j++) { tA[j] = make_float4(0,0,0,0); tB[j] = make_float4(0,0,0,0); }

    #pragma unroll 2
    for (int k0 = 0; k0 < HH; k0 += 4) {
        float4 v[4];
        #pragma unroll
        for (int j = 0; j < 4; j++)
            v[j] = *(const float4*)(Sv + (nb + 32 * j) * AS_STRIDE + k0);
        #pragma unroll
        for (int kk = 0; kk < 4; kk++) {
            float4 w0 = Wls4[(k0 + kk) * 16 + 2 * g];
            float4 w1 = Wls4[(k0 + kk) * 16 + 2 * g + 1];
            #pragma unroll
            for (int j = 0; j < 4; j++) {
                float s = (kk == 0) ? v[j].x : (kk == 1) ? v[j].y : (kk == 2) ? v[j].z : v[j].w;
                tA[j].x += s * w0.x; tA[j].y += s * w0.y; tA[j].z += s * w0.z; tA[j].w += s * w0.w;
                tB[j].x += s * w1.x; tB[j].y += s * w1.y; tB[j].z += s * w1.z; tB[j].w += s * w1.w;
            }
        }
    }
    if (g < 5) {
        float4 blA = ((const float4*)bl)[2 * g];
        float4 blB = (g < 4) ? ((const float4*)bl)[2 * g + 1] : ((const float4*)bl)[9];
        #pragma unroll
        for (int j = 0; j < 4; j++) {
            int gn = base + nb + 32 * j;
            if (gn >= NN) continue;
            float4 oA, oB;
            oA.x = tA[j].x + blA.x; oA.y = tA[j].y + blA.y; oA.z = tA[j].z + blA.z; oA.w = tA[j].w + blA.w;
            oB.x = tB[j].x + blB.x; oB.y = tB[j].y + blB.y; oB.z = tB[j].z + blB.z; oB.w = tB[j].w + blB.w;
            float4* po = (float4*)(out + gn * OUT_C + 8 * g);
            po[0] = oA;
            po[1] = oB;
        }
    }
}

// ---------------------------------------------------------------------------
extern "C" void kernel_launch(void* const* d_in, const int* in_sizes, int n_in,
                              void* d_out, int out_size) {
    const float* x     = (const float*)d_in[0];
    const int*   eiRaw = (const int*)d_in[1];
    const float* nf    = (const float*)d_in[2];
    const float* We    = (const float*)d_in[3];
    const float* be    = (const float*)d_in[4];
    const float* W     = (const float*)d_in[5];
    const float* U     = (const float*)d_in[6];
    const float* bU    = (const float*)d_in[7];
    const float* gamma = (const float*)d_in[8];
    const float* beta  = (const float*)d_in[9];
    const float* Wl    = (const float*)d_in[10];
    const float* bl    = (const float*)d_in[11];
    float* out = (float*)d_out;

    size_t front_smem = (size_t)(128 * XS_STRIDE + IN_C * HH) * sizeof(float);
    size_t fused_smem = (size_t)(128 * AS_STRIDE + 2 * HH * HH) * sizeof(float);
    size_t out_smem   = (size_t)(128 * AS_STRIDE + HH * HH) * sizeof(float);
    cudaFuncSetAttribute(k_front, cudaFuncAttributeMaxDynamicSharedMemorySize, (int)front_smem);
    cudaFuncSetAttribute(k_fused, cudaFuncAttributeMaxDynamicSharedMemorySize, (int)fused_smem);
    cudaFuncSetAttribute(k_out,   cudaFuncAttributeMaxDynamicSharedMemorySize, (int)out_smem);

    k_probe<<<1, 32>>>(eiRaw);
    k_convert<<<(EE + 255) / 256, 256>>>(eiRaw);
    k_prep<<<(IN_C * HH + 255) / 256, 256>>>(We, U, W, Wl);

    int nodeBlocks = (NN + 127) / 128;
    k_front<<<nodeBlocks, 256, front_smem>>>(x, be, bU, nf);

    for (int s = 0; s < 4; s++) {
        k_edge<<<1184, 256>>>(gamma, beta);
        k_fused<<<nodeBlocks, 256, fused_smem>>>(W, nf, s < 3 ? 1 : 0);
    }

    k_out<<<nodeBlocks, 256, out_smem>>>(nf, bl, out);
}

// round 7
// speedup vs baseline: 1.4097x; 1.0395x over previous
#include <cuda_runtime.h>
#include <cuda_fp16.h>
#include <cstdint>

#define NN 50000
#define EE 1600000
#define IN_C 128
#define HH 64
#define OUT_C 40
#define ALPHA 0.8f
#define LN_EPS 1e-5f

#define XS_STRIDE 129
#define AS_STRIDE 68

// Scratch (device globals)
__device__ float4 g_xh4[NN * 16];
__device__ float4 g_xU4[NN * 16];
__device__ uint2  g_h2 [NN * 16];   // h in fp16: 16 x uint2 (=4 half each) = 64 ch
__device__ float4 g_a4 [NN * 16];
__device__ float4 g_z4 [NN * 16];
__device__ int2   g_rc [EE];
__device__ int    g_is64;
// pre-transposed weights
__device__ float  g_WeT[IN_C * HH];   // [k][c] = We[c][k]
__device__ float  g_UT [HH * HH];     // [k][c] = U[c][k]
__device__ float  g_WT [HH * HH];     // [k][c] = W[c][k]
__device__ float  g_WlT[HH * HH];     // [k][c] = Wl[c][k], zero-padded c>=40

#define g_xh ((float*)g_xh4)
#define g_a  ((float*)g_a4)
#define g_z  ((float*)g_z4)

__device__ __forceinline__ float htanh(float x) {
    float y;
    asm("tanh.approx.f32 %0, %1;" : "=f"(y) : "f"(x));
    return y;
}

__device__ __forceinline__ unsigned pack2(float a, float b) {
    __half2 h = __floats2half2_rn(a, b);
    return *reinterpret_cast<unsigned*>(&h);
}

// Pack 8 floats (2 float4) -> uint4 of halves, store to g_h2 for node gn, group g.
__device__ __forceinline__ void store_h16(int gn, int g, const float4& hA, const float4& hB) {
    uint4 u;
    u.x = pack2(hA.x, hA.y);
    u.y = pack2(hA.z, hA.w);
    u.z = pack2(hB.x, hB.y);
    u.w = pack2(hB.z, hB.w);
    ((uint4*)g_h2)[gn * 8 + g] = u;
}

// ---------------------------------------------------------------------------
__global__ void k_probe(const int* __restrict__ ei_raw) {
    if (threadIdx.x == 0 && blockIdx.x == 0) {
        int allzero = 1;
        #pragma unroll
        for (int i = 1; i < 128; i += 2) allzero &= (ei_raw[i] == 0);
        g_is64 = allzero;
    }
}

__global__ __launch_bounds__(256) void k_convert(const int* __restrict__ ei_raw) {
    int e = blockIdx.x * blockDim.x + threadIdx.x;
    if (e >= EE) return;
    int r, c;
    if (g_is64) {
        const long long* p = (const long long*)ei_raw;
        r = (int)p[e];
        c = (int)p[EE + e];
    } else {
        r = ei_raw[e];
        c = ei_raw[EE + e];
    }
    g_rc[e] = make_int2(r, c);
}

// ---------------------------------------------------------------------------
__global__ __launch_bounds__(256) void k_prep(const float* __restrict__ We,
                                              const float* __restrict__ U,
                                              const float* __restrict__ W,
                                              const float* __restrict__ Wl) {
    int idx = blockIdx.x * blockDim.x + threadIdx.x;
    if (idx < IN_C * HH) {
        int k = idx >> 6, c = idx & 63;
        g_WeT[idx] = We[c * IN_C + k];
    }
    if (idx < HH * HH) {
        int k = idx >> 6, c = idx & 63;
        g_UT[idx]  = U[c * HH + k];
        g_WT[idx]  = W[c * HH + k];
        g_WlT[idx] = (c < OUT_C) ? Wl[c * HH + k] : 0.0f;
    }
}

// ---------------------------------------------------------------------------
// Front: xh = x@We^T + be ; xU = deg*(xh@U^T + bU) ; h0 = nf*xU ; z=0 ; a=0
// 128 nodes/block, 256 threads; thread: 4 nodes x 8 channels.
// dyn smem: Xs[128*129] | Wb[128*64]  (~96.5KB)
// ---------------------------------------------------------------------------
__global__ __launch_bounds__(256) void k_front(const float* __restrict__ x,
                                               const float* __restrict__ be,
                                               const float* __restrict__ bU,
                                               const float* __restrict__ nf) {
    extern __shared__ float sm[];
    float* Xs = sm;                   // 128 * 129
    float* Wb = sm + 128 * XS_STRIDE; // 128 * 64 (phase1: WeT; phase2: UT)

    int tid = threadIdx.x;
    int g = tid & 7, nb = tid >> 3;
    int base = blockIdx.x * 128;

    for (int idx = tid; idx < 128 * IN_C; idx += 256) {
        int n = idx >> 7, k = idx & 127;
        Xs[n * XS_STRIDE + k] = (base + n < NN) ? x[(base + n) * IN_C + k] : 0.0f;
    }
    for (int idx = tid; idx < IN_C * HH; idx += 256) Wb[idx] = g_WeT[idx];
    __syncthreads();

    const float4* Wb4 = (const float4*)Wb;
    float4 beA = ((const float4*)be)[2 * g], beB = ((const float4*)be)[2 * g + 1];
    float4 bUA = ((const float4*)bU)[2 * g], bUB = ((const float4*)bU)[2 * g + 1];

    float4 aA[4], aB[4];
    #pragma unroll
    for (int j = 0; j < 4; j++) { aA[j] = make_float4(0,0,0,0); aB[j] = make_float4(0,0,0,0); }

    #pragma unroll 4
    for (int k = 0; k < IN_C; k++) {
        float4 w0 = Wb4[k * 16 + 2 * g];
        float4 w1 = Wb4[k * 16 + 2 * g + 1];
        #pragma unroll
        for (int j = 0; j < 4; j++) {
            float v = Xs[(nb + 32 * j) * XS_STRIDE + k];
            aA[j].x += v * w0.x; aA[j].y += v * w0.y; aA[j].z += v * w0.z; aA[j].w += v * w0.w;
            aB[j].x += v * w1.x; aB[j].y += v * w1.y; aB[j].z += v * w1.z; aB[j].w += v * w1.w;
        }
    }
    #pragma unroll
    for (int j = 0; j < 4; j++) {
        aA[j].x += beA.x; aA[j].y += beA.y; aA[j].z += beA.z; aA[j].w += beA.w;
        aB[j].x += beB.x; aB[j].y += beB.y; aB[j].z += beB.z; aB[j].w += beB.w;
        int gn = base + nb + 32 * j;
        if (gn < NN) { g_xh4[gn * 16 + 2 * g] = aA[j]; g_xh4[gn * 16 + 2 * g + 1] = aB[j]; }
    }

    __syncthreads();
    #pragma unroll
    for (int j = 0; j < 4; j++) {
        float* rr = Xs + (nb + 32 * j) * XS_STRIDE + 8 * g;
        rr[0]=aA[j].x; rr[1]=aA[j].y; rr[2]=aA[j].z; rr[3]=aA[j].w;
        rr[4]=aB[j].x; rr[5]=aB[j].y; rr[6]=aB[j].z; rr[7]=aB[j].w;
    }
    for (int idx = tid; idx < HH * HH; idx += 256) Wb[idx] = g_UT[idx];
    __syncthreads();

    float4 cA[4], cB[4];
    #pragma unroll
    for (int j = 0; j < 4; j++) { cA[j] = make_float4(0,0,0,0); cB[j] = make_float4(0,0,0,0); }
    #pragma unroll 4
    for (int k = 0; k < HH; k++) {
        float4 w0 = Wb4[k * 16 + 2 * g];
        float4 w1 = Wb4[k * 16 + 2 * g + 1];
        #pragma unroll
        for (int j = 0; j < 4; j++) {
            float v = Xs[(nb + 32 * j) * XS_STRIDE + k];
            cA[j].x += v * w0.x; cA[j].y += v * w0.y; cA[j].z += v * w0.z; cA[j].w += v * w0.w;
            cB[j].x += v * w1.x; cB[j].y += v * w1.y; cB[j].z += v * w1.z; cB[j].w += v * w1.w;
        }
    }
    float4 z4 = make_float4(0,0,0,0);
    #pragma unroll
    for (int j = 0; j < 4; j++) {
        int gn = base + nb + 32 * j;
        if (gn >= NN) continue;
        float nfv = nf[gn];
        float deg = 1.0f / nfv;
        if (isinf(deg)) deg = 0.0f;
        float4 xuA, xuB, hA, hB;
        xuA.x = deg * (cA[j].x + bUA.x); xuA.y = deg * (cA[j].y + bUA.y);
        xuA.z = deg * (cA[j].z + bUA.z); xuA.w = deg * (cA[j].w + bUA.w);
        xuB.x = deg * (cB[j].x + bUB.x); xuB.y = deg * (cB[j].y + bUB.y);
        xuB.z = deg * (cB[j].z + bUB.z); xuB.w = deg * (cB[j].w + bUB.w);
        hA.x = nfv * xuA.x; hA.y = nfv * xuA.y; hA.z = nfv * xuA.z; hA.w = nfv * xuA.w;
        hB.x = nfv * xuB.x; hB.y = nfv * xuB.y; hB.z = nfv * xuB.z; hB.w = nfv * xuB.w;
        g_xU4[gn * 16 + 2 * g] = xuA; g_xU4[gn * 16 + 2 * g + 1] = xuB;
        store_h16(gn, g, hA, hB);
        g_z4 [gn * 16 + 2 * g] = z4;  g_z4 [gn * 16 + 2 * g + 1] = z4;
        g_a4 [gn * 16 + 2 * g] = z4;  g_a4 [gn * 16 + 2 * g + 1] = z4;
    }
}

// ---------------------------------------------------------------------------
// Edge: 16-lane groups; h in fp16 (8B/lane per endpoint).
// m = LN(tanh(h[r]-h[c])); a[r] += m; a[c] -= m   (nf applied in k_fused)
// ---------------------------------------------------------------------------
__global__ __launch_bounds__(256) void k_edge(const float* __restrict__ gamma,
                                              const float* __restrict__ beta) {
    int tid = blockIdx.x * blockDim.x + threadIdx.x;
    int l = threadIdx.x & 15;
    int hw = tid >> 4;
    int nhw = (gridDim.x * blockDim.x) >> 4;
    unsigned hmask = 0xFFFFu << (threadIdx.x & 16);

    const float4 gm = *(const float4*)(gamma + 4 * l);
    const float4 bt = *(const float4*)(beta + 4 * l);

    for (int e = hw; e < EE; e += nhw) {
        int2 rc = __ldg(&g_rc[e]);
        uint2 ur = __ldg(&g_h2[rc.x * 16 + l]);
        uint2 uc = __ldg(&g_h2[rc.y * 16 + l]);

        __half2 d0 = __hsub2(*(__half2*)&ur.x, *(__half2*)&uc.x);
        __half2 d1 = __hsub2(*(__half2*)&ur.y, *(__half2*)&uc.y);
        float2 f0 = __half22float2(d0);
        float2 f1 = __half22float2(d1);

        float t0 = htanh(f0.x);
        float t1 = htanh(f0.y);
        float t2 = htanh(f1.x);
        float t3 = htanh(f1.y);

        float s  = t0 + t1 + t2 + t3;
        float s2 = t0 * t0 + t1 * t1 + t2 * t2 + t3 * t3;
        #pragma unroll
        for (int m = 8; m; m >>= 1) {
            s  += __shfl_xor_sync(hmask, s,  m);
            s2 += __shfl_xor_sync(hmask, s2, m);
        }
        float mean = s * (1.0f / 64.0f);
        float var  = s2 * (1.0f / 64.0f) - mean * mean;
        float rstd = rsqrtf(var + LN_EPS);

        float m0 = gm.x * ((t0 - mean) * rstd) + bt.x;
        float m1 = gm.y * ((t1 - mean) * rstd) + bt.y;
        float m2 = gm.z * ((t2 - mean) * rstd) + bt.z;
        float m3 = gm.w * ((t3 - mean) * rstd) + bt.w;

        float* ar = (float*)(g_a4 + rc.x * 16 + l);
        float* ac = (float*)(g_a4 + rc.y * 16 + l);
        asm volatile("red.global.add.v4.f32 [%0], {%1,%2,%3,%4};"
                     :: "l"(ar), "f"(m0), "f"(m1), "f"(m2), "f"(m3) : "memory");
        asm volatile("red.global.add.v4.f32 [%0], {%1,%2,%3,%4};"
                     :: "l"(ac), "f"(-m0), "f"(-m1), "f"(-m2), "f"(-m3) : "memory");
    }
}

// ---------------------------------------------------------------------------
// Fused step: a' = nf.*a_raw ; t = a'@W ; z = -ALPHA*t + (1-ALPHA)*z ;
//             h = nf*(z@W^T + xU) (fp16) ; a_raw = 0
// dyn smem: As[128*68] | Ws[64*64] | Wts[64*64]
// ---------------------------------------------------------------------------
__global__ __launch_bounds__(256) void k_fused(const float* __restrict__ W,
                                               const float* __restrict__ nf,
                                               int compute_h) {
    extern __shared__ float sm[];
    float* As  = sm;                    // 128 * 68
    float* Ws  = sm + 128 * AS_STRIDE;  // 64 * 64
    float* Wts = Ws + HH * HH;          // 64 * 64

    int tid = threadIdx.x;
    int g = tid & 7, nb = tid >> 3;
    int base = blockIdx.x * 128;

    for (int idx = tid; idx < 128 * HH; idx += 256) {
        int n = idx >> 6, c = idx & 63;
        int gn = base + n;
        As[n * AS_STRIDE + c] = (gn < NN) ? nf[gn] * g_a[gn * HH + c] : 0.0f;
    }
    for (int idx = tid; idx < HH * HH; idx += 256) { Ws[idx] = W[idx]; Wts[idx] = g_WT[idx]; }
    __syncthreads();

    const float4* Ws4  = (const float4*)Ws;
    const float4* Wts4 = (const float4*)Wts;

    float4 tA[4], tB[4];
    #pragma unroll
    for (int j = 0; j < 4; j++) { tA[j] = make_float4(0,0,0,0); tB[j] = make_float4(0,0,0,0); }

    #pragma unroll 2
    for (int k0 = 0; k0 < HH; k0 += 4) {
        float4 v[4];
        #pragma unroll
        for (int j = 0; j < 4; j++)
            v[j] = *(const float4*)(As + (nb + 32 * j) * AS_STRIDE + k0);
        #pragma unroll
        for (int kk = 0; kk < 4; kk++) {
            float4 w0 = Ws4[(k0 + kk) * 16 + 2 * g];
            float4 w1 = Ws4[(k0 + kk) * 16 + 2 * g + 1];
            #pragma unroll
            for (int j = 0; j < 4; j++) {
                float s = (kk == 0) ? v[j].x : (kk == 1) ? v[j].y : (kk == 2) ? v[j].z : v[j].w;
                tA[j].x += s * w0.x; tA[j].y += s * w0.y; tA[j].z += s * w0.z; tA[j].w += s * w0.w;
                tB[j].x += s * w1.x; tB[j].y += s * w1.y; tB[j].z += s * w1.z; tB[j].w += s * w1.w;
            }
        }
    }

    float4 znA[4], znB[4];
    #pragma unroll
    for (int j = 0; j < 4; j++) {
        int gn = base + nb + 32 * j;
        if (gn >= NN) { znA[j] = make_float4(0,0,0,0); znB[j] = make_float4(0,0,0,0); continue; }
        float4 zA = g_z4[gn * 16 + 2 * g], zB = g_z4[gn * 16 + 2 * g + 1];
        znA[j].x = -ALPHA * tA[j].x + (1.0f - ALPHA) * zA.x;
        znA[j].y = -ALPHA * tA[j].y + (1.0f - ALPHA) * zA.y;
        znA[j].z = -ALPHA * tA[j].z + (1.0f - ALPHA) * zA.z;
        znA[j].w = -ALPHA * tA[j].w + (1.0f - ALPHA) * zA.w;
        znB[j].x = -ALPHA * tB[j].x + (1.0f - ALPHA) * zB.x;
        znB[j].y = -ALPHA * tB[j].y + (1.0f - ALPHA) * zB.y;
        znB[j].z = -ALPHA * tB[j].z + (1.0f - ALPHA) * zB.z;
        znB[j].w = -ALPHA * tB[j].w + (1.0f - ALPHA) * zB.w;
        g_z4[gn * 16 + 2 * g] = znA[j];
        g_z4[gn * 16 + 2 * g + 1] = znB[j];
    }

    __syncthreads();
    #pragma unroll
    for (int j = 0; j < 4; j++) {
        float* rr = As + (nb + 32 * j) * AS_STRIDE + 8 * g;
        rr[0]=znA[j].x; rr[1]=znA[j].y; rr[2]=znA[j].z; rr[3]=znA[j].w;
        rr[4]=znB[j].x; rr[5]=znB[j].y; rr[6]=znB[j].z; rr[7]=znB[j].w;
    }
    __syncthreads();

    if (compute_h) {
        #pragma unroll
        for (int j = 0; j < 4; j++) { tA[j] = make_float4(0,0,0,0); tB[j] = make_float4(0,0,0,0); }
        #pragma unroll 2
        for (int k0 = 0; k0 < HH; k0 += 4) {
            float4 v[4];
            #pragma unroll
            for (int j = 0; j < 4; j++)
                v[j] = *(const float4*)(As + (nb + 32 * j) * AS_STRIDE + k0);
            #pragma unroll
            for (int kk = 0; kk < 4; kk++) {
                float4 w0 = Wts4[(k0 + kk) * 16 + 2 * g];
                float4 w1 = Wts4[(k0 + kk) * 16 + 2 * g + 1];
                #pragma unroll
                for (int j = 0; j < 4; j++) {
                    float s = (kk == 0) ? v[j].x : (kk == 1) ? v[j].y : (kk == 2) ? v[j].z : v[j].w;
                    tA[j].x += s * w0.x; tA[j].y += s * w0.y; tA[j].z += s * w0.z; tA[j].w += s * w0.w;
                    tB[j].x += s * w1.x; tB[j].y += s * w1.y; tB[j].z += s * w1.z; tB[j].w += s * w1.w;
                }
            }
        }
        #pragma unroll
        for (int j = 0; j < 4; j++) {
            int gn = base + nb + 32 * j;
            if (gn >= NN) continue;
            float nfv = nf[gn];
            float4 xuA = g_xU4[gn * 16 + 2 * g], xuB = g_xU4[gn * 16 + 2 * g + 1];
            float4 hA, hB;
            hA.x = nfv * (tA[j].x + xuA.x); hA.y = nfv * (tA[j].y + xuA.y);
            hA.z = nfv * (tA[j].z + xuA.z); hA.w = nfv * (tA[j].w + xuA.w);
            hB.x = nfv * (tB[j].x + xuB.x); hB.y = nfv * (tB[j].y + xuB.y);
            hB.z = nfv * (tB[j].z + xuB.z); hB.w = nfv * (tB[j].w + xuB.w);
            store_h16(gn, g, hA, hB);
        }
    }

    float4 zero4 = make_float4(0,0,0,0);
    #pragma unroll
    for (int j = 0; j < 4; j++) {
        int gn = base + nb + 32 * j;
        if (gn >= NN) continue;
        g_a4[gn * 16 + 2 * g] = zero4;
        g_a4[gn * 16 + 2 * g + 1] = zero4;
    }
}

// ---------------------------------------------------------------------------
// Out: out = (nf*z + xh) @ Wlast^T + blast  (Wl padded to 64 cols)
// ---------------------------------------------------------------------------
__global__ __launch_bounds__(256) void k_out(const float* __restrict__ nf,
                                             const float* __restrict__ bl,
                                             float* __restrict__ out) {
    extern __shared__ float sm[];
    float* Sv  = sm;                    // 128 * 68
    float* Wls = sm + 128 * AS_STRIDE;  // 64 * 64

    int tid = threadIdx.x;
    int g = tid & 7, nb = tid >> 3;
    int base = blockIdx.x * 128;

    for (int idx = tid; idx < 128 * HH; idx += 256) {
        int n = idx >> 6, c = idx & 63;
        int gn = base + n;
        Sv[n * AS_STRIDE + c] = (gn < NN) ? (nf[gn] * g_z[gn * HH + c] + g_xh[gn * HH + c]) : 0.0f;
    }
    for (int idx = tid; idx < HH * HH; idx += 256) Wls[idx] = g_WlT[idx];
    __syncthreads();

    const float4* Wls4 = (const float4*)Wls;
    float4 tA[4], tB[4];
    #pragma unroll
    for (int j = 0; j < 4; j++) { tA[j] = make_float4(0,0,0,0); tB[j] = make_float4(0,0,0,0); }

    #pragma unroll 2
    for (int k0 = 0; k0 < HH; k0 += 4) {
        float4 v[4];
        #pragma unroll
        for (int j = 0; j < 4; j++)
            v[j] = *(const float4*)(Sv + (nb + 32 * j) * AS_STRIDE + k0);
        #pragma unroll
        for (int kk = 0; kk < 4; kk++) {
            float4 w0 = Wls4[(k0 + kk) * 16 + 2 * g];
            float4 w1 = Wls4[(k0 + kk) * 16 + 2 * g + 1];
            #pragma unroll
            for (int j = 0; j < 4; j++) {
                float s = (kk == 0) ? v[j].x : (kk == 1) ? v[j].y : (kk == 2) ? v[j].z : v[j].w;
                tA[j].x += s * w0.x; tA[j].y += s * w0.y; tA[j].z += s * w0.z; tA[j].w += s * w0.w;
                tB[j].x += s * w1.x; tB[j].y += s * w1.y; tB[j].z += s * w1.z; tB[j].w += s * w1.w;
            }
        }
    }
    if (g < 5) {
        float4 blA = ((const float4*)bl)[2 * g];
        float4 blB = (g < 4) ? ((const float4*)bl)[2 * g + 1] : ((const float4*)bl)[9];
        #pragma unroll
        for (int j = 0; j < 4; j++) {
            int gn = base + nb + 32 * j;
            if (gn >= NN) continue;
            float4 oA, oB;
            oA.x = tA[j].x + blA.x; oA.y = tA[j].y + blA.y; oA.z = tA[j].z + blA.z; oA.w = tA[j].w + blA.w;
            oB.x = tB[j].x + blB.x; oB.y = tB[j].y + blB.y; oB.z = tB[j].z + blB.z; oB.w = tB[j].w + blB.w;
            float4* po = (float4*)(out + gn * OUT_C + 8 * g);
            po[0] = oA;
            po[1] = oB;
        }
    }
}

// ---------------------------------------------------------------------------
extern "C" void kernel_launch(void* const* d_in, const int* in_sizes, int n_in,
                              void* d_out, int out_size) {
    const float* x     = (const float*)d_in[0];
    const int*   eiRaw = (const int*)d_in[1];
    const float* nf    = (const float*)d_in[2];
    const float* We    = (const float*)d_in[3];
    const float* be    = (const float*)d_in[4];
    const float* W     = (const float*)d_in[5];
    const float* U     = (const float*)d_in[6];
    const float* bU    = (const float*)d_in[7];
    const float* gamma = (const float*)d_in[8];
    const float* beta  = (const float*)d_in[9];
    const float* Wl    = (const float*)d_in[10];
    const float* bl    = (const float*)d_in[11];
    float* out = (float*)d_out;

    size_t front_smem = (size_t)(128 * XS_STRIDE + IN_C * HH) * sizeof(float);
    size_t fused_smem = (size_t)(128 * AS_STRIDE + 2 * HH * HH) * sizeof(float);
    size_t out_smem   = (size_t)(128 * AS_STRIDE + HH * HH) * sizeof(float);
    cudaFuncSetAttribute(k_front, cudaFuncAttributeMaxDynamicSharedMemorySize, (int)front_smem);
    cudaFuncSetAttribute(k_fused, cudaFuncAttributeMaxDynamicSharedMemorySize, (int)fused_smem);
    cudaFuncSetAttribute(k_out,   cudaFuncAttributeMaxDynamicSharedMemorySize, (int)out_smem);

    k_probe<<<1, 32>>>(eiRaw);
    k_convert<<<(EE + 255) / 256, 256>>>(eiRaw);
    k_prep<<<(IN_C * HH + 255) / 256, 256>>>(We, U, W, Wl);

    int nodeBlocks = (NN + 127) / 128;
    k_front<<<nodeBlocks, 256, front_smem>>>(x, be, bU, nf);

    for (int s = 0; s < 4; s++) {
        k_edge<<<1184, 256>>>(gamma, beta);
        k_fused<<<nodeBlocks, 256, fused_smem>>>(W, nf, s < 3 ? 1 : 0);
    }

    k_out<<<nodeBlocks, 256, out_smem>>>(nf, bl, out);
}